// round 6
// baseline (speedup 1.0000x reference)
#include <cuda_runtime.h>
#include <cuda_fp16.h>
#include <cstdint>

// ============================================================================
// Problem constants
// ============================================================================
#define BATCH 4096
#define HSZ   2048
#define KDIM  4096          // HSZ + INPUT_SIZE
#define NROWS 8192          // 4*HSZ gate-blocked weight rows

// GEMM tiling
#define TM 128
#define TN 128              // 4 gates x 32 j-columns
#define BK 64
#define KT (KDIM / BK)      // 64 k-iterations
#define STAGES 4
#define STAGE_A (TM * BK * 2)          // 16384
#define STAGE_B (TN * BK * 2)          // 16384
#define STAGE_BYTES (STAGE_A + STAGE_B)  // 32768
#define SMEM_BYTES (STAGES * STAGE_BYTES + 1024)   // 132096 (1KB align pad)

// fp16 staging (device globals: allocation-free scratch)
__device__ __half g_W16[(size_t)NROWS * KDIM];   // 64 MB
__device__ __half g_A16[(size_t)BATCH * KDIM];   // 32 MB

#define SW128(x) ((x) ^ (((x) >> 3) & 0x70))

// ============================================================================
// PTX helpers (sm_80-era -> valid under compute_100 target)
// ============================================================================
__device__ __forceinline__ uint32_t s2u(const void* p) {
    uint32_t a;
    asm("{ .reg .u64 t; cvta.to.shared.u64 t, %1; cvt.u32.u64 %0, t; }"
        : "=r"(a) : "l"(p));
    return a;
}
__device__ __forceinline__ void cpa16(uint32_t dst, const void* src) {
    asm volatile("cp.async.cg.shared.global [%0], [%1], 16;" :: "r"(dst), "l"(src));
}
__device__ __forceinline__ void cpa_commit() {
    asm volatile("cp.async.commit_group;" ::: "memory");
}
template <int N>
__device__ __forceinline__ void cpa_wait() {
    asm volatile("cp.async.wait_group %0;" :: "n"(N) : "memory");
}
__device__ __forceinline__ void ldsm4(uint32_t (&r)[4], uint32_t addr) {
    asm volatile("ldmatrix.sync.aligned.m8n8.x4.shared.b16 {%0,%1,%2,%3}, [%4];"
                 : "=r"(r[0]), "=r"(r[1]), "=r"(r[2]), "=r"(r[3]) : "r"(addr));
}
__device__ __forceinline__ void mma16816(float (&c)[4], const uint32_t (&a)[4],
                                         uint32_t b0, uint32_t b1) {
    asm volatile(
        "mma.sync.aligned.m16n8k16.row.col.f32.f16.f16.f32 "
        "{%0,%1,%2,%3}, {%4,%5,%6,%7}, {%8,%9}, {%0,%1,%2,%3};"
        : "+f"(c[0]), "+f"(c[1]), "+f"(c[2]), "+f"(c[3])
        : "r"(a[0]), "r"(a[1]), "r"(a[2]), "r"(a[3]), "r"(b0), "r"(b1));
}

// ============================================================================
// fp32 -> fp16 conversion kernels
// ============================================================================
__global__ void __launch_bounds__(256) k_convW(
    const float4* __restrict__ Wf, const float4* __restrict__ Wi,
    const float4* __restrict__ Wg, const float4* __restrict__ Wo)
{
    uint32_t i = blockIdx.x * 256u + threadIdx.x;      // < 8,388,608 float4s
    uint32_t gate = i >> 21;                            // 2,097,152 per gate
    uint32_t off  = i & 2097151u;
    float4 v = (gate == 0 ? Wf : gate == 1 ? Wi : gate == 2 ? Wg : Wo)[off];
    union { __half2 h2[2]; uint2 u; } pk;
    pk.h2[0] = __floats2half2_rn(v.x, v.y);
    pk.h2[1] = __floats2half2_rn(v.z, v.w);
    *reinterpret_cast<uint2*>(g_W16 + ((size_t)gate * 8388608u + (size_t)off * 4u)) = pk.u;
}

__global__ void __launch_bounds__(256) k_convA(
    const float* __restrict__ h, const float* __restrict__ x)
{
    uint32_t i = blockIdx.x * 256u + threadIdx.x;      // < 4,194,304 float4s
    uint32_t b = i >> 10;                               // 1024 float4 per row
    uint32_t q = i & 1023u;
    const float* src = (q < 512u) ? (h + (size_t)b * 2048u + q * 4u)
                                  : (x + (size_t)b * 2048u + (q - 512u) * 4u);
    float4 v = *reinterpret_cast<const float4*>(src);
    union { __half2 h2[2]; uint2 u; } pk;
    pk.h2[0] = __floats2half2_rn(v.x, v.y);
    pk.h2[1] = __floats2half2_rn(v.z, v.w);
    *reinterpret_cast<uint2*>(g_A16 + ((size_t)b * 4096u + (size_t)q * 4u)) = pk.u;
}

// ============================================================================
// Fused LSTM: 128x128 CTA tile (4 gates x 32 j), mma.sync + cp.async pipeline
// grid = 2048 (bx>>6 = m-tile, bx&63 = j-tile), block = 256
// ============================================================================
__global__ void __launch_bounds__(256, 1) k_lstm(
    const float* __restrict__ cIn,
    const float* __restrict__ bf, const float* __restrict__ bi,
    const float* __restrict__ bg, const float* __restrict__ bo,
    float* __restrict__ out)
{
    extern __shared__ char smem[];
    const uint32_t raw  = s2u(smem);
    const uint32_t base = (raw + 1023u) & ~1023u;     // 1KB aligned
    const uint32_t tid  = threadIdx.x;
    const int wid  = tid >> 5;
    const int lane = tid & 31;
    const int mw = wid >> 2;          // 0..1  (M warp)
    const int nw = wid & 3;           // 0..3  (= gate index)

    const int mb = blockIdx.x >> 6;
    const int nb = blockIdx.x & 63;
    const int m0 = mb * TM;           // batch row offset
    const int j0 = nb * 32;           // j offset within each gate

    // ---------------- stage loader ----------------
    auto load_stage = [&](int s, int kt) {
        const uint32_t sA = base + s * STAGE_BYTES;
        const uint32_t sB = sA + STAGE_A;
        const int k0 = kt * BK;
#pragma unroll
        for (int i = 0; i < 8; ++i) {                 // 2048 chunks / 256 thr
            const int q = (i << 8) + (int)tid;
            if (q < 1024) {                            // A: 128 rows x 8 chunks
                const int r = q >> 3, kc = q & 7;
                cpa16(sA + SW128((uint32_t)(q << 4)),
                      g_A16 + (size_t)(m0 + r) * KDIM + k0 + kc * 8);
            } else {                                   // B: 128 n-rows x 8 chunks
                const int p = q - 1024;
                const int n = p >> 3, kc = p & 7;
                const int wrow = (n >> 5) * HSZ + j0 + (n & 31);
                cpa16(sB + SW128((uint32_t)(p << 4)),
                      g_W16 + (size_t)wrow * KDIM + k0 + kc * 8);
            }
        }
    };

    // ---------------- prologue ----------------
#pragma unroll
    for (int s = 0; s < STAGES - 1; ++s) {
        load_stage(s, s);
        cpa_commit();
    }

    float acc[4][4][4];
#pragma unroll
    for (int a = 0; a < 4; ++a)
#pragma unroll
        for (int b = 0; b < 4; ++b)
#pragma unroll
            for (int c = 0; c < 4; ++c) acc[a][b][c] = 0.f;

    // lane-derived ldmatrix offsets.
    // A and B both stored [row][k] with K contiguous (128B rows): non-trans
    // ldmatrix x4, lanes 0-15 -> rows (k0-7 chunk), lanes 16-31 -> +16B (k8-15).
    const int ldRow = lane & 15;
    const int ldKB  = (lane >> 4) << 4;               // 0 or 16 bytes

    // ---------------- main loop ----------------
    for (int kt = 0; kt < KT; ++kt) {
        cpa_wait<STAGES - 2>();
        __syncthreads();

        const int ns = kt + STAGES - 1;
        if (ns < KT) load_stage(ns & (STAGES - 1), ns);
        cpa_commit();

        const uint32_t sA = base + (kt & (STAGES - 1)) * STAGE_BYTES;
        const uint32_t sB = sA + STAGE_A;

#pragma unroll
        for (int ks = 0; ks < 4; ++ks) {              // 4 x k16 per BK=64
            const uint32_t kb = ks << 5;              // 32B per k16
            uint32_t afr[4][4];
#pragma unroll
            for (int mf = 0; mf < 4; ++mf)
                ldsm4(afr[mf], sA + SW128((uint32_t)((mw * 64 + mf * 16 + ldRow) * 128)
                                          + kb + ldKB));
            // B: matrices [0]=(n0-7,k0-7) [1]=(n8-15,k0-7) [2]=(n0-7,k8-15) [3]=(n8-15,k8-15)
            uint32_t bfr[2][4];
#pragma unroll
            for (int pr = 0; pr < 2; ++pr)
                ldsm4(bfr[pr], sB + SW128((uint32_t)((nw * 32 + pr * 16 + ldRow) * 128)
                                          + kb + ldKB));
#pragma unroll
            for (int mf = 0; mf < 4; ++mf)
#pragma unroll
                for (int nf = 0; nf < 4; ++nf) {
                    const int pr = nf >> 1, sub = nf & 1;
                    mma16816(acc[mf][nf], afr[mf], bfr[pr][sub], bfr[pr][sub + 2]);
                }
        }
    }

    // ---------------- epilogue ----------------
    __syncthreads();                                  // all compute done before alias
    float* sg = reinterpret_cast<float*>(smem + (base - raw));   // [128][132]

#pragma unroll
    for (int mf = 0; mf < 4; ++mf)
#pragma unroll
        for (int nf = 0; nf < 4; ++nf) {
            const int r0 = mw * 64 + mf * 16 + (lane >> 2);
            const int cc = nw * 32 + nf * 8 + ((lane & 3) << 1);
            *reinterpret_cast<float2*>(sg + r0 * 132 + cc) =
                make_float2(acc[mf][nf][0], acc[mf][nf][1]);
            *reinterpret_cast<float2*>(sg + (r0 + 8) * 132 + cc) =
                make_float2(acc[mf][nf][2], acc[mf][nf][3]);
        }
    __syncthreads();

#pragma unroll
    for (int e = 0; e < 16; ++e) {
        const int id = (e << 8) + (int)tid;           // 0..4095
        const int m = id >> 5;                        // 0..127
        const int j = id & 31;                        // 0..31
        const float zf = sg[m * 132 +       j] + __ldg(bf + j0 + j);
        const float zi = sg[m * 132 + 32  + j] + __ldg(bi + j0 + j);
        const float zg = sg[m * 132 + 64  + j] + __ldg(bg + j0 + j);
        const float zo = sg[m * 132 + 96  + j] + __ldg(bo + j0 + j);
        const float ft = 1.f / (1.f + __expf(-zf));
        const float it = 1.f / (1.f + __expf(-zi));
        const float gt = 2.f / (1.f + __expf(-2.f * zg)) - 1.f;
        const float ot = 1.f / (1.f + __expf(-zo));
        const size_t go = (size_t)(m0 + m) * HSZ + j0 + j;
        const float cn = ft * __ldg(cIn + go) + it * gt;
        const float hn = ot * (2.f / (1.f + __expf(-2.f * cn)) - 1.f);
        out[go] = hn;
        out[(size_t)BATCH * HSZ + go] = cn;
    }
}

// ============================================================================
// Launch
// ============================================================================
extern "C" void kernel_launch(void* const* d_in, const int* in_sizes, int n_in,
                              void* d_out, int out_size) {
    const float* x  = (const float*)d_in[0];
    const float* h  = (const float*)d_in[1];
    const float* c  = (const float*)d_in[2];
    const float* Wf = (const float*)d_in[3];
    const float* bf = (const float*)d_in[4];
    const float* Wi = (const float*)d_in[5];
    const float* bi = (const float*)d_in[6];
    const float* Wg = (const float*)d_in[7];
    const float* bg = (const float*)d_in[8];
    const float* Wo = (const float*)d_in[9];
    const float* bo = (const float*)d_in[10];
    float* out = (float*)d_out;

    cudaFuncSetAttribute(k_lstm, cudaFuncAttributeMaxDynamicSharedMemorySize,
                         SMEM_BYTES);

    k_convW<<<32768, 256>>>((const float4*)Wf, (const float4*)Wi,
                            (const float4*)Wg, (const float4*)Wo);
    k_convA<<<16384, 256>>>(h, x);
    k_lstm<<<2048, 256, SMEM_BYTES>>>(c, bf, bi, bg, bo, out);
}

// round 8
// speedup vs baseline: 1.1052x; 1.1052x over previous
#include <cuda_runtime.h>
#include <cuda_fp16.h>
#include <cstdint>

// ============================================================================
// Problem constants
// ============================================================================
#define BATCH 4096
#define HSZ   2048
#define KDIM  4096          // HSZ + INPUT_SIZE
#define NROWS 8192          // 4*HSZ gate-blocked weight rows

// GEMM tiling: CTA 256(M) x 128(N = 4 gates x 32 j), BK=64
#define TM 256
#define TN 128
#define BK 64
#define KT (KDIM / BK)      // 64 k-iterations
#define STAGES 4
#define STAGE_A (TM * BK * 2)            // 32768
#define STAGE_B (TN * BK * 2)            // 16384
#define STAGE_BYTES (STAGE_A + STAGE_B)  // 49152
#define SMEM_BYTES (STAGES * STAGE_BYTES + 1024)   // 197632

// fp16 staging (device globals: allocation-free scratch)
__device__ __half g_W16[(size_t)NROWS * KDIM];   // 64 MB
__device__ __half g_A16[(size_t)BATCH * KDIM];   // 32 MB

#define SW128(x) ((x) ^ (((x) >> 3) & 0x70))

// ============================================================================
// PTX helpers (sm_80-era -> valid under compute_100 target)
// ============================================================================
__device__ __forceinline__ uint32_t s2u(const void* p) {
    uint32_t a;
    asm("{ .reg .u64 t; cvta.to.shared.u64 t, %1; cvt.u32.u64 %0, t; }"
        : "=r"(a) : "l"(p));
    return a;
}
__device__ __forceinline__ void cpa16(uint32_t dst, const void* src) {
    asm volatile("cp.async.cg.shared.global [%0], [%1], 16;" :: "r"(dst), "l"(src));
}
__device__ __forceinline__ void cpa_commit() {
    asm volatile("cp.async.commit_group;" ::: "memory");
}
template <int N>
__device__ __forceinline__ void cpa_wait() {
    asm volatile("cp.async.wait_group %0;" :: "n"(N) : "memory");
}
__device__ __forceinline__ void ldsm4(uint32_t (&r)[4], uint32_t addr) {
    asm volatile("ldmatrix.sync.aligned.m8n8.x4.shared.b16 {%0,%1,%2,%3}, [%4];"
                 : "=r"(r[0]), "=r"(r[1]), "=r"(r[2]), "=r"(r[3]) : "r"(addr));
}
__device__ __forceinline__ void mma16816(float (&c)[4], const uint32_t (&a)[4],
                                         uint32_t b0, uint32_t b1) {
    asm volatile(
        "mma.sync.aligned.m16n8k16.row.col.f32.f16.f16.f32 "
        "{%0,%1,%2,%3}, {%4,%5,%6,%7}, {%8,%9}, {%0,%1,%2,%3};"
        : "+f"(c[0]), "+f"(c[1]), "+f"(c[2]), "+f"(c[3])
        : "r"(a[0]), "r"(a[1]), "r"(a[2]), "r"(a[3]), "r"(b0), "r"(b1));
}

// ============================================================================
// fp32 -> fp16 conversion kernels
// ============================================================================
__global__ void __launch_bounds__(256) k_convW(
    const float4* __restrict__ Wf, const float4* __restrict__ Wi,
    const float4* __restrict__ Wg, const float4* __restrict__ Wo)
{
    uint32_t i = blockIdx.x * 256u + threadIdx.x;      // < 8,388,608 float4s
    uint32_t gate = i >> 21;                            // 2,097,152 per gate
    uint32_t off  = i & 2097151u;
    float4 v = (gate == 0 ? Wf : gate == 1 ? Wi : gate == 2 ? Wg : Wo)[off];
    union { __half2 h2[2]; uint2 u; } pk;
    pk.h2[0] = __floats2half2_rn(v.x, v.y);
    pk.h2[1] = __floats2half2_rn(v.z, v.w);
    *reinterpret_cast<uint2*>(g_W16 + ((size_t)gate * 8388608u + (size_t)off * 4u)) = pk.u;
}

__global__ void __launch_bounds__(256) k_convA(
    const float* __restrict__ h, const float* __restrict__ x)
{
    uint32_t i = blockIdx.x * 256u + threadIdx.x;      // < 4,194,304 float4s
    uint32_t b = i >> 10;                               // 1024 float4 per row
    uint32_t q = i & 1023u;
    const float* src = (q < 512u) ? (h + (size_t)b * 2048u + q * 4u)
                                  : (x + (size_t)b * 2048u + (q - 512u) * 4u);
    float4 v = *reinterpret_cast<const float4*>(src);
    union { __half2 h2[2]; uint2 u; } pk;
    pk.h2[0] = __floats2half2_rn(v.x, v.y);
    pk.h2[1] = __floats2half2_rn(v.z, v.w);
    *reinterpret_cast<uint2*>(g_A16 + ((size_t)b * 4096u + (size_t)q * 4u)) = pk.u;
}

// ============================================================================
// Fused LSTM: 256x128 CTA tile, 64x64 warp tiles (warp grid 4x2), 256 threads
// grid = 1024 (bx>>6 = m-tile, bx&63 = j-tile)
// ============================================================================
__global__ void __launch_bounds__(256, 1) k_lstm(
    const float* __restrict__ cIn,
    const float* __restrict__ bf, const float* __restrict__ bi,
    const float* __restrict__ bg, const float* __restrict__ bo,
    float* __restrict__ out)
{
    extern __shared__ char smem[];
    const uint32_t raw  = s2u(smem);
    const uint32_t base = (raw + 1023u) & ~1023u;     // 1KB aligned
    const uint32_t tid  = threadIdx.x;
    const int wid  = tid >> 5;
    const int lane = tid & 31;
    const int mw = wid >> 1;          // 0..3  (M warp: 64 rows each)
    const int nw = wid & 1;           // 0..1  (N warp: 64 cols each)

    const int mb = blockIdx.x >> 6;
    const int nb = blockIdx.x & 63;
    const int m0 = mb * TM;           // batch row offset
    const int j0 = nb * 32;           // j offset within each gate

    // ---------------- stage loader (3072 16B chunks / 256 thr = 12 each) ----
    auto load_stage = [&](int s, int kt) {
        const uint32_t sA = base + s * STAGE_BYTES;
        const uint32_t sB = sA + STAGE_A;
        const int k0 = kt * BK;
#pragma unroll
        for (int i = 0; i < 12; ++i) {
            const int q = (i << 8) + (int)tid;
            if (q < 2048) {                            // A: 256 rows x 8 chunks
                const int r = q >> 3, kc = q & 7;
                cpa16(sA + SW128((uint32_t)(q << 4)),
                      g_A16 + (size_t)(m0 + r) * KDIM + k0 + kc * 8);
            } else {                                   // B: 128 n-rows x 8 chunks
                const int p = q - 2048;
                const int n = p >> 3, kc = p & 7;
                const int wrow = (n >> 5) * HSZ + j0 + (n & 31);
                cpa16(sB + SW128((uint32_t)(p << 4)),
                      g_W16 + (size_t)wrow * KDIM + k0 + kc * 8);
            }
        }
    };

    // ---------------- prologue ----------------
#pragma unroll
    for (int s = 0; s < STAGES - 1; ++s) {
        load_stage(s, s);
        cpa_commit();
    }

    float acc[4][8][4];
#pragma unroll
    for (int a = 0; a < 4; ++a)
#pragma unroll
        for (int b = 0; b < 8; ++b)
#pragma unroll
            for (int c = 0; c < 4; ++c) acc[a][b][c] = 0.f;

    // ldmatrix lane addressing (non-trans, rows 128B apart, K contiguous):
    // lanes 0-15 -> 16 rows (k0-7 chunk), lanes 16-31 -> same rows +16B (k8-15)
    const int ldRow = lane & 15;
    const int ldKB  = (lane >> 4) << 4;

    // ---------------- main loop ----------------
    for (int kt = 0; kt < KT; ++kt) {
        cpa_wait<STAGES - 2>();
        __syncthreads();

        const int ns = kt + STAGES - 1;
        if (ns < KT) load_stage(ns & (STAGES - 1), ns);
        cpa_commit();

        const uint32_t sA = base + (kt & (STAGES - 1)) * STAGE_BYTES;
        const uint32_t sB = sA + STAGE_A;

#pragma unroll
        for (int ks = 0; ks < 4; ++ks) {              // 4 x k16 per BK=64
            const uint32_t kb = ks << 5;              // 32B per k16
            uint32_t afr[4][4];
#pragma unroll
            for (int mf = 0; mf < 4; ++mf)
                ldsm4(afr[mf], sA + SW128((uint32_t)((mw * 64 + mf * 16 + ldRow) * 128)
                                          + kb + ldKB));
            // B frag groups: [pr][0]=(n0-7,k0-7) [1]=(n8-15,k0-7)
            //                [2]=(n0-7,k8-15)    [3]=(n8-15,k8-15)
            uint32_t bfr[4][4];
#pragma unroll
            for (int pr = 0; pr < 4; ++pr)
                ldsm4(bfr[pr], sB + SW128((uint32_t)((nw * 64 + pr * 16 + ldRow) * 128)
                                          + kb + ldKB));
#pragma unroll
            for (int mf = 0; mf < 4; ++mf)
#pragma unroll
                for (int nf = 0; nf < 8; ++nf) {
                    const int pr = nf >> 1, sub = nf & 1;
                    mma16816(acc[mf][nf], afr[mf], bfr[pr][sub], bfr[pr][sub + 2]);
                }
        }
    }

    // ---------------- epilogue ----------------
    __syncthreads();                                  // compute done before alias
    float* sg = reinterpret_cast<float*>(smem + (base - raw));   // [256][132]

#pragma unroll
    for (int mf = 0; mf < 4; ++mf)
#pragma unroll
        for (int nf = 0; nf < 8; ++nf) {
            const int r0 = mw * 64 + mf * 16 + (lane >> 2);
            const int cc = nw * 64 + nf * 8 + ((lane & 3) << 1);
            *reinterpret_cast<float2*>(sg + r0 * 132 + cc) =
                make_float2(acc[mf][nf][0], acc[mf][nf][1]);
            *reinterpret_cast<float2*>(sg + (r0 + 8) * 132 + cc) =
                make_float2(acc[mf][nf][2], acc[mf][nf][3]);
        }
    __syncthreads();

#pragma unroll
    for (int e = 0; e < 32; ++e) {
        const int id = (e << 8) + (int)tid;           // 0..8191
        const int m = id >> 5;                        // 0..255
        const int j = id & 31;                        // 0..31
        const float zf = sg[m * 132 +       j] + __ldg(bf + j0 + j);
        const float zi = sg[m * 132 + 32  + j] + __ldg(bi + j0 + j);
        const float zg = sg[m * 132 + 64  + j] + __ldg(bg + j0 + j);
        const float zo = sg[m * 132 + 96  + j] + __ldg(bo + j0 + j);
        const float ft = 1.f / (1.f + __expf(-zf));
        const float it = 1.f / (1.f + __expf(-zi));
        const float gt = 2.f / (1.f + __expf(-2.f * zg)) - 1.f;
        const float ot = 1.f / (1.f + __expf(-zo));
        const size_t go = (size_t)(m0 + m) * HSZ + j0 + j;
        const float cn = ft * __ldg(cIn + go) + it * gt;
        const float hn = ot * (2.f / (1.f + __expf(-2.f * cn)) - 1.f);
        out[go] = hn;
        out[(size_t)BATCH * HSZ + go] = cn;
    }
}

// ============================================================================
// Launch
// ============================================================================
extern "C" void kernel_launch(void* const* d_in, const int* in_sizes, int n_in,
                              void* d_out, int out_size) {
    const float* x  = (const float*)d_in[0];
    const float* h  = (const float*)d_in[1];
    const float* c  = (const float*)d_in[2];
    const float* Wf = (const float*)d_in[3];
    const float* bf = (const float*)d_in[4];
    const float* Wi = (const float*)d_in[5];
    const float* bi = (const float*)d_in[6];
    const float* Wg = (const float*)d_in[7];
    const float* bg = (const float*)d_in[8];
    const float* Wo = (const float*)d_in[9];
    const float* bo = (const float*)d_in[10];
    float* out = (float*)d_out;

    cudaFuncSetAttribute(k_lstm, cudaFuncAttributeMaxDynamicSharedMemorySize,
                         SMEM_BYTES);

    k_convW<<<32768, 256>>>((const float4*)Wf, (const float4*)Wi,
                            (const float4*)Wg, (const float4*)Wo);
    k_convA<<<16384, 256>>>(h, x);
    k_lstm<<<1024, 256, SMEM_BYTES>>>(c, bf, bi, bg, bo, out);
}

// round 9
// speedup vs baseline: 1.2440x; 1.1255x over previous
#include <cuda_runtime.h>
#include <cuda_fp16.h>
#include <cstdint>

// ============================================================================
// Problem constants
// ============================================================================
#define BATCH 4096
#define HSZ   2048
#define KDIM  4096          // HSZ + INPUT_SIZE
#define NROWS 8192          // 4*HSZ gate-blocked weight rows

// GEMM tiling: CTA 128(M) x 256(N = 4 gates x 64 j), BK=64, 512 threads
#define TM 128
#define TN 256
#define BK 64
#define KT (KDIM / BK)      // 64 k-iterations
#define STAGES 4
#define STAGE_A (TM * BK * 2)            // 16384
#define STAGE_B (TN * BK * 2)            // 32768
#define STAGE_BYTES (STAGE_A + STAGE_B)  // 49152
#define SMEM_BYTES (STAGES * STAGE_BYTES + 1024)   // 197632

// fp16 staging (device globals: allocation-free scratch)
__device__ __half g_W16[(size_t)NROWS * KDIM];   // 64 MB
__device__ __half g_A16[(size_t)BATCH * KDIM];   // 32 MB

#define SW128(x) ((x) ^ (((x) >> 3) & 0x70))

// ============================================================================
// PTX helpers (sm_80-era -> valid under compute_100 target)
// ============================================================================
__device__ __forceinline__ uint32_t s2u(const void* p) {
    uint32_t a;
    asm("{ .reg .u64 t; cvta.to.shared.u64 t, %1; cvt.u32.u64 %0, t; }"
        : "=r"(a) : "l"(p));
    return a;
}
__device__ __forceinline__ void cpa16(uint32_t dst, const void* src) {
    asm volatile("cp.async.cg.shared.global [%0], [%1], 16;" :: "r"(dst), "l"(src));
}
__device__ __forceinline__ void cpa_commit() {
    asm volatile("cp.async.commit_group;" ::: "memory");
}
template <int N>
__device__ __forceinline__ void cpa_wait() {
    asm volatile("cp.async.wait_group %0;" :: "n"(N) : "memory");
}
__device__ __forceinline__ void ldsm4(uint32_t (&r)[4], uint32_t addr) {
    asm volatile("ldmatrix.sync.aligned.m8n8.x4.shared.b16 {%0,%1,%2,%3}, [%4];"
                 : "=r"(r[0]), "=r"(r[1]), "=r"(r[2]), "=r"(r[3]) : "r"(addr));
}
__device__ __forceinline__ void mma16816(float (&c)[4], const uint32_t (&a)[4],
                                         uint32_t b0, uint32_t b1) {
    asm volatile(
        "mma.sync.aligned.m16n8k16.row.col.f32.f16.f16.f32 "
        "{%0,%1,%2,%3}, {%4,%5,%6,%7}, {%8,%9}, {%0,%1,%2,%3};"
        : "+f"(c[0]), "+f"(c[1]), "+f"(c[2]), "+f"(c[3])
        : "r"(a[0]), "r"(a[1]), "r"(a[2]), "r"(a[3]), "r"(b0), "r"(b1));
}

// ============================================================================
// fp32 -> fp16 conversion kernels
// ============================================================================
__global__ void __launch_bounds__(256) k_convW(
    const float4* __restrict__ Wf, const float4* __restrict__ Wi,
    const float4* __restrict__ Wg, const float4* __restrict__ Wo)
{
    uint32_t i = blockIdx.x * 256u + threadIdx.x;      // < 8,388,608 float4s
    uint32_t gate = i >> 21;                            // 2,097,152 per gate
    uint32_t off  = i & 2097151u;
    float4 v = (gate == 0 ? Wf : gate == 1 ? Wi : gate == 2 ? Wg : Wo)[off];
    union { __half2 h2[2]; uint2 u; } pk;
    pk.h2[0] = __floats2half2_rn(v.x, v.y);
    pk.h2[1] = __floats2half2_rn(v.z, v.w);
    *reinterpret_cast<uint2*>(g_W16 + ((size_t)gate * 8388608u + (size_t)off * 4u)) = pk.u;
}

__global__ void __launch_bounds__(256) k_convA(
    const float* __restrict__ h, const float* __restrict__ x)
{
    uint32_t i = blockIdx.x * 256u + threadIdx.x;      // < 4,194,304 float4s
    uint32_t b = i >> 10;                               // 1024 float4 per row
    uint32_t q = i & 1023u;
    const float* src = (q < 512u) ? (h + (size_t)b * 2048u + q * 4u)
                                  : (x + (size_t)b * 2048u + (q - 512u) * 4u);
    float4 v = *reinterpret_cast<const float4*>(src);
    union { __half2 h2[2]; uint2 u; } pk;
    pk.h2[0] = __floats2half2_rn(v.x, v.y);
    pk.h2[1] = __floats2half2_rn(v.z, v.w);
    *reinterpret_cast<uint2*>(g_A16 + ((size_t)b * 4096u + (size_t)q * 4u)) = pk.u;
}

// ============================================================================
// Fused LSTM: 128x256 CTA tile, 32x64 warp tiles (warp grid 4x4), 512 threads
// grid = 1024 (bx>>5 = m-tile, bx&31 = j-tile)
// ============================================================================
__global__ void __launch_bounds__(512, 1) k_lstm(
    const float* __restrict__ cIn,
    const float* __restrict__ bf, const float* __restrict__ bi,
    const float* __restrict__ bg, const float* __restrict__ bo,
    float* __restrict__ out)
{
    extern __shared__ char smem[];
    const uint32_t raw  = s2u(smem);
    const uint32_t base = (raw + 1023u) & ~1023u;     // 1KB aligned
    const uint32_t tid  = threadIdx.x;
    const int wid  = tid >> 5;
    const int lane = tid & 31;
    const int mw = wid >> 2;          // 0..3  (M warp: 32 rows each)
    const int nw = wid & 3;           // 0..3  (N warp: 64 cols each)

    const int mb = blockIdx.x >> 5;
    const int nb = blockIdx.x & 31;
    const int m0 = mb * TM;           // batch row offset
    const int j0 = nb * 64;           // j offset within each gate

    // ---------------- stage loader (3072 16B chunks / 512 thr = 6 each) ----
    auto load_stage = [&](int s, int kt) {
        const uint32_t sA = base + s * STAGE_BYTES;
        const uint32_t sB = sA + STAGE_A;
        const int k0 = kt * BK;
#pragma unroll
        for (int i = 0; i < 6; ++i) {
            const int q = (i << 9) + (int)tid;
            if (q < 1024) {                            // A: 128 rows x 8 chunks
                const int r = q >> 3, kc = q & 7;
                cpa16(sA + SW128((uint32_t)(q << 4)),
                      g_A16 + (size_t)(m0 + r) * KDIM + k0 + kc * 8);
            } else {                                   // B: 256 n-rows x 8 chunks
                const int p = q - 1024;
                const int n = p >> 3, kc = p & 7;
                const int wrow = (n >> 6) * HSZ + j0 + (n & 63);
                cpa16(sB + SW128((uint32_t)(p << 4)),
                      g_W16 + (size_t)wrow * KDIM + k0 + kc * 8);
            }
        }
    };

    // ---------------- prologue ----------------
#pragma unroll
    for (int s = 0; s < STAGES - 1; ++s) {
        load_stage(s, s);
        cpa_commit();
    }

    float acc[2][8][4];
#pragma unroll
    for (int a = 0; a < 2; ++a)
#pragma unroll
        for (int b = 0; b < 8; ++b)
#pragma unroll
            for (int c = 0; c < 4; ++c) acc[a][b][c] = 0.f;

    // ldmatrix lane addressing (non-trans, rows 128B apart, K contiguous):
    // lanes 0-15 -> 16 rows (k0-7 chunk), lanes 16-31 -> same rows +16B (k8-15)
    const int ldRow = lane & 15;
    const int ldKB  = (lane >> 4) << 4;

    // ---------------- main loop ----------------
    for (int kt = 0; kt < KT; ++kt) {
        cpa_wait<STAGES - 2>();
        __syncthreads();

        const int ns = kt + STAGES - 1;
        if (ns < KT) load_stage(ns & (STAGES - 1), ns);
        cpa_commit();

        const uint32_t sA = base + (kt & (STAGES - 1)) * STAGE_BYTES;
        const uint32_t sB = sA + STAGE_A;

#pragma unroll
        for (int ks = 0; ks < 4; ++ks) {              // 4 x k16 per BK=64
            const uint32_t kb = ks << 5;              // 32B per k16
            uint32_t afr[2][4];
#pragma unroll
            for (int mf = 0; mf < 2; ++mf)
                ldsm4(afr[mf], sA + SW128((uint32_t)((mw * 32 + mf * 16 + ldRow) * 128)
                                          + kb + ldKB));
            // B frag groups: [pr][0]=(n0-7,k0-7) [1]=(n8-15,k0-7)
            //                [2]=(n0-7,k8-15)    [3]=(n8-15,k8-15)
            uint32_t bfr[4][4];
#pragma unroll
            for (int pr = 0; pr < 4; ++pr)
                ldsm4(bfr[pr], sB + SW128((uint32_t)((nw * 64 + pr * 16 + ldRow) * 128)
                                          + kb + ldKB));
#pragma unroll
            for (int mf = 0; mf < 2; ++mf)
#pragma unroll
                for (int nf = 0; nf < 8; ++nf) {
                    const int pr = nf >> 1, sub = nf & 1;
                    mma16816(acc[mf][nf], afr[mf], bfr[pr][sub], bfr[pr][sub + 2]);
                }
        }
    }

    // ---------------- epilogue ----------------
    __syncthreads();                                  // compute done before alias
    float* sg = reinterpret_cast<float*>(smem + (base - raw));   // [128][260]

#pragma unroll
    for (int mf = 0; mf < 2; ++mf)
#pragma unroll
        for (int nf = 0; nf < 8; ++nf) {
            const int r0 = mw * 32 + mf * 16 + (lane >> 2);
            const int cc = nw * 64 + nf * 8 + ((lane & 3) << 1);
            *reinterpret_cast<float2*>(sg + r0 * 260 + cc) =
                make_float2(acc[mf][nf][0], acc[mf][nf][1]);
            *reinterpret_cast<float2*>(sg + (r0 + 8) * 260 + cc) =
                make_float2(acc[mf][nf][2], acc[mf][nf][3]);
        }
    __syncthreads();

#pragma unroll
    for (int e = 0; e < 16; ++e) {
        const int id = (e << 9) + (int)tid;           // 0..8191
        const int m = id >> 6;                        // 0..127
        const int j = id & 63;                        // 0..63
        const float zf = sg[m * 260 +        j] + __ldg(bf + j0 + j);
        const float zi = sg[m * 260 + 64   + j] + __ldg(bi + j0 + j);
        const float zg = sg[m * 260 + 128  + j] + __ldg(bg + j0 + j);
        const float zo = sg[m * 260 + 192  + j] + __ldg(bo + j0 + j);
        const float ft = 1.f / (1.f + __expf(-zf));
        const float it = 1.f / (1.f + __expf(-zi));
        const float gt = 2.f / (1.f + __expf(-2.f * zg)) - 1.f;
        const float ot = 1.f / (1.f + __expf(-zo));
        const size_t go = (size_t)(m0 + m) * HSZ + j0 + j;
        const float cn = ft * __ldg(cIn + go) + it * gt;
        const float hn = ot * (2.f / (1.f + __expf(-2.f * cn)) - 1.f);
        out[go] = hn;
        out[(size_t)BATCH * HSZ + go] = cn;
    }
}

// ============================================================================
// Launch
// ============================================================================
extern "C" void kernel_launch(void* const* d_in, const int* in_sizes, int n_in,
                              void* d_out, int out_size) {
    const float* x  = (const float*)d_in[0];
    const float* h  = (const float*)d_in[1];
    const float* c  = (const float*)d_in[2];
    const float* Wf = (const float*)d_in[3];
    const float* bf = (const float*)d_in[4];
    const float* Wi = (const float*)d_in[5];
    const float* bi = (const float*)d_in[6];
    const float* Wg = (const float*)d_in[7];
    const float* bg = (const float*)d_in[8];
    const float* Wo = (const float*)d_in[9];
    const float* bo = (const float*)d_in[10];
    float* out = (float*)d_out;

    cudaFuncSetAttribute(k_lstm, cudaFuncAttributeMaxDynamicSharedMemorySize,
                         SMEM_BYTES);

    k_convW<<<32768, 256>>>((const float4*)Wf, (const float4*)Wi,
                            (const float4*)Wg, (const float4*)Wo);
    k_convA<<<16384, 256>>>(h, x);
    k_lstm<<<1024, 512, SMEM_BYTES>>>(c, bf, bi, bg, bo, out);
}

// round 10
// speedup vs baseline: 1.3040x; 1.0483x over previous
#include <cuda_runtime.h>
#include <cuda_fp16.h>
#include <cstdint>

// ============================================================================
// Problem constants
// ============================================================================
#define BATCH 4096
#define HSZ   2048
#define KDIM  4096          // HSZ + INPUT_SIZE
#define NROWS 8192          // 4*HSZ gate-blocked weight rows

// GEMM tiling: CTA 128(M) x 256(N = 4 gates x 64 j), BK=64, 512 threads
#define TM 128
#define TN 256
#define BK 64
#define KT (KDIM / BK)      // 64 k-iterations
#define STAGES 4
#define STAGE_A (TM * BK * 2)            // 16384
#define STAGE_B (TN * BK * 2)            // 32768
#define STAGE_BYTES (STAGE_A + STAGE_B)  // 49152
#define CTRL_OFF (STAGES * STAGE_BYTES)  // 196608
#define SMEM_BYTES (1024 + CTRL_OFF + 64)

// fp16 staging in TILED+SWIZZLED layout (ready for cp.async.bulk):
//   g_A16t: tile t = mb*64+kt  (mb 0..31, kt 0..63), 128 rows x 64 k, 16KB each
//   g_W16t: tile t = nb*64+kt  (nb 0..31, kt 0..63), 256 nrows x 64 k, 32KB each
__device__ __half g_A16t[(size_t)BATCH * KDIM];   // 32 MB
__device__ __half g_W16t[(size_t)NROWS * KDIM];   // 64 MB

#define SW128(x) ((x) ^ (((x) >> 3) & 0x70))

// ============================================================================
// PTX helpers (base sm_90 features -> valid under compute_100 target)
// ============================================================================
__device__ __forceinline__ uint32_t s2u(const void* p) {
    uint32_t a;
    asm("{ .reg .u64 t; cvta.to.shared.u64 t, %1; cvt.u32.u64 %0, t; }"
        : "=r"(a) : "l"(p));
    return a;
}
#define MBAR_INIT(a, c) \
    asm volatile("mbarrier.init.shared.b64 [%0], %1;" :: "r"(a), "r"(c) : "memory")
#define MBAR_EXPECT_TX(a, b) \
    asm volatile("mbarrier.arrive.expect_tx.shared.b64 _, [%0], %1;" \
                 :: "r"(a), "r"(b) : "memory")
#define MBAR_WAIT(addr, ph) do {                                               \
    uint32_t _a = (addr), _p = (ph), _d;                                       \
    asm volatile("{ .reg .pred p; "                                            \
        "mbarrier.try_wait.parity.acquire.cta.shared::cta.b64 p, [%1], %2; "   \
        "selp.b32 %0, 1, 0, p; }" : "=r"(_d) : "r"(_a), "r"(_p) : "memory");   \
    if (!_d) {                                                                 \
        asm volatile("{ .reg .pred P; "                                        \
        "LW_%=: mbarrier.try_wait.parity.acquire.cta.shared::cta.b64 P, [%0], %1, 0x989680; " \
        "@P bra LD_%=; bra LW_%=; LD_%=: }" :: "r"(_a), "r"(_p) : "memory");   \
    } } while (0)

__device__ __forceinline__ void bulk_g2s(uint32_t dst, const void* src,
                                         uint32_t bytes, uint32_t mbar) {
    asm volatile(
        "cp.async.bulk.shared::cta.global.mbarrier::complete_tx::bytes "
        "[%0], [%1], %2, [%3];"
        :: "r"(dst), "l"(src), "r"(bytes), "r"(mbar) : "memory");
}
__device__ __forceinline__ void ldsm4(uint32_t (&r)[4], uint32_t addr) {
    asm volatile("ldmatrix.sync.aligned.m8n8.x4.shared.b16 {%0,%1,%2,%3}, [%4];"
                 : "=r"(r[0]), "=r"(r[1]), "=r"(r[2]), "=r"(r[3]) : "r"(addr));
}
__device__ __forceinline__ void mma16816(float (&c)[4], const uint32_t (&a)[4],
                                         uint32_t b0, uint32_t b1) {
    asm volatile(
        "mma.sync.aligned.m16n8k16.row.col.f32.f16.f16.f32 "
        "{%0,%1,%2,%3}, {%4,%5,%6,%7}, {%8,%9}, {%0,%1,%2,%3};"
        : "+f"(c[0]), "+f"(c[1]), "+f"(c[2]), "+f"(c[3])
        : "r"(a[0]), "r"(a[1]), "r"(a[2]), "r"(a[3]), "r"(b0), "r"(b1));
}

// ============================================================================
// fp32 -> fp16 conversion into tiled+swizzled layout
// ============================================================================
// A: chunk c -> tile(mb,kt), r(0..127), kc(0..7). 16B per chunk.
__global__ void __launch_bounds__(256) k_convA(
    const float* __restrict__ h, const float* __restrict__ x)
{
    const uint32_t c = blockIdx.x * 256u + threadIdx.x;   // < 2,097,152
    const uint32_t tile = c >> 10;                         // mb*64 + kt
    const uint32_t wi = c & 1023u;
    const uint32_t r = wi >> 3, kc = wi & 7u;
    const uint32_t mb = tile >> 6, kt = tile & 63u;
    const uint32_t m = mb * 128u + r;
    const uint32_t kg = kt * 64u + kc * 8u;
    const float* src = (kg < 2048u) ? (h + (size_t)m * 2048u + kg)
                                    : (x + (size_t)m * 2048u + (kg - 2048u));
    float4 v0 = *reinterpret_cast<const float4*>(src);
    float4 v1 = *reinterpret_cast<const float4*>(src + 4);
    union { __half2 h2[4]; uint4 u; } pk;
    pk.h2[0] = __floats2half2_rn(v0.x, v0.y);
    pk.h2[1] = __floats2half2_rn(v0.z, v0.w);
    pk.h2[2] = __floats2half2_rn(v1.x, v1.y);
    pk.h2[3] = __floats2half2_rn(v1.z, v1.w);
    char* dst = reinterpret_cast<char*>(g_A16t) + (size_t)tile * 16384u
              + SW128(r * 128u + kc * 16u);
    *reinterpret_cast<uint4*>(dst) = pk.u;
}

// W: chunk c -> tile(nb,kt), n_local(0..255)=gate*64+jl, kc(0..7)
__global__ void __launch_bounds__(256) k_convW(
    const float* __restrict__ Wf, const float* __restrict__ Wi,
    const float* __restrict__ Wg, const float* __restrict__ Wo)
{
    const uint32_t c = blockIdx.x * 256u + threadIdx.x;   // < 4,194,304
    const uint32_t tile = c >> 11;                         // nb*64 + kt
    const uint32_t wi = c & 2047u;
    const uint32_t nl = wi >> 3, kc = wi & 7u;
    const uint32_t nb = tile >> 6, kt = tile & 63u;
    const uint32_t gate = nl >> 6, jl = nl & 63u;
    const float* W = (gate == 0 ? Wf : gate == 1 ? Wi : gate == 2 ? Wg : Wo);
    const float* src = W + (size_t)(nb * 64u + jl) * KDIM + kt * 64u + kc * 8u;
    float4 v0 = *reinterpret_cast<const float4*>(src);
    float4 v1 = *reinterpret_cast<const float4*>(src + 4);
    union { __half2 h2[4]; uint4 u; } pk;
    pk.h2[0] = __floats2half2_rn(v0.x, v0.y);
    pk.h2[1] = __floats2half2_rn(v0.z, v0.w);
    pk.h2[2] = __floats2half2_rn(v1.x, v1.y);
    pk.h2[3] = __floats2half2_rn(v1.z, v1.w);
    char* dst = reinterpret_cast<char*>(g_W16t) + (size_t)tile * 32768u
              + SW128(nl * 128u + kc * 16u);
    *reinterpret_cast<uint4*>(dst) = pk.u;
}

// ============================================================================
// Fused LSTM: 128x256 CTA tile, 32x64 warp tiles (4x4 warps), 512 threads,
// cp.async.bulk (single-issuer) + mbarrier pipeline.
// grid = 1024 (bx>>5 = m-tile, bx&31 = j-tile)
// ============================================================================
__global__ void __launch_bounds__(512, 1) k_lstm(
    const float* __restrict__ cIn,
    const float* __restrict__ bf, const float* __restrict__ bi,
    const float* __restrict__ bg, const float* __restrict__ bo,
    float* __restrict__ out)
{
    extern __shared__ char smem[];
    const uint32_t raw  = s2u(smem);
    const uint32_t base = (raw + 1023u) & ~1023u;     // 1KB aligned stages
    const uint32_t ctrl = base + CTRL_OFF;            // 4 mbarriers (8B each)
    const uint32_t tid  = threadIdx.x;
    const int wid  = tid >> 5;
    const int lane = tid & 31;
    const int mw = wid >> 2;          // 0..3  (M warp: 32 rows)
    const int nw = wid & 3;           // 0..3  (N warp: 64 cols)

    const int mb = blockIdx.x >> 5;
    const int nb = blockIdx.x & 31;
    const int m0 = mb * TM;
    const int j0 = nb * 64;

    const char* gA = reinterpret_cast<const char*>(g_A16t)
                   + (size_t)(mb * 64) * 16384u;       // + kt*16384
    const char* gB = reinterpret_cast<const char*>(g_W16t)
                   + (size_t)(nb * 64) * 32768u;       // + kt*32768

    if (tid == 0) {
#pragma unroll
        for (int s = 0; s < STAGES; ++s) MBAR_INIT(ctrl + s * 8, 1);
    }
    __syncthreads();

    // prologue: issue stages 0..2
    if (tid == 0) {
#pragma unroll
        for (int s = 0; s < STAGES - 1; ++s) {
            const uint32_t sb = base + s * STAGE_BYTES;
            MBAR_EXPECT_TX(ctrl + s * 8, STAGE_BYTES);
            bulk_g2s(sb, gA + (size_t)s * 16384u, STAGE_A, ctrl + s * 8);
            bulk_g2s(sb + STAGE_A, gB + (size_t)s * 32768u, STAGE_B, ctrl + s * 8);
        }
    }

    float acc[2][8][4];
#pragma unroll
    for (int a = 0; a < 2; ++a)
#pragma unroll
        for (int b = 0; b < 8; ++b)
#pragma unroll
            for (int c = 0; c < 4; ++c) acc[a][b][c] = 0.f;

    const int ldRow = lane & 15;
    const int ldKB  = (lane >> 4) << 4;

    // ---------------- main loop ----------------
    for (int kt = 0; kt < KT; ++kt) {
        const int s = kt & (STAGES - 1);
        MBAR_WAIT(ctrl + s * 8, (kt >> 2) & 1);
        __syncthreads();                              // all done with kt-1's buffer

        if (tid == 0) {
            const int ns = kt + STAGES - 1;
            if (ns < KT) {
                const int s2 = ns & (STAGES - 1);
                const uint32_t sb = base + s2 * STAGE_BYTES;
                MBAR_EXPECT_TX(ctrl + s2 * 8, STAGE_BYTES);
                bulk_g2s(sb, gA + (size_t)ns * 16384u, STAGE_A, ctrl + s2 * 8);
                bulk_g2s(sb + STAGE_A, gB + (size_t)ns * 32768u, STAGE_B,
                         ctrl + s2 * 8);
            }
        }

        const uint32_t sA = base + s * STAGE_BYTES;
        const uint32_t sB = sA + STAGE_A;

#pragma unroll
        for (int ks = 0; ks < 4; ++ks) {              // 4 x k16 per BK=64
            const uint32_t kb = ks << 5;
            uint32_t afr[2][4];
#pragma unroll
            for (int mf = 0; mf < 2; ++mf)
                ldsm4(afr[mf], sA + SW128((uint32_t)((mw * 32 + mf * 16 + ldRow) * 128)
                                          + kb + ldKB));
            uint32_t bfr[4][4];
#pragma unroll
            for (int pr = 0; pr < 4; ++pr)
                ldsm4(bfr[pr], sB + SW128((uint32_t)((nw * 64 + pr * 16 + ldRow) * 128)
                                          + kb + ldKB));
#pragma unroll
            for (int mf = 0; mf < 2; ++mf)
#pragma unroll
                for (int nf = 0; nf < 8; ++nf) {
                    const int pr = nf >> 1, sub = nf & 1;
                    mma16816(acc[mf][nf], afr[mf], bfr[pr][sub], bfr[pr][sub + 2]);
                }
        }
    }

    // ---------------- epilogue ----------------
    __syncthreads();                                  // compute done before alias
    float* sg = reinterpret_cast<float*>(smem + (base - raw));   // [128][260]

#pragma unroll
    for (int mf = 0; mf < 2; ++mf)
#pragma unroll
        for (int nf = 0; nf < 8; ++nf) {
            const int r0 = mw * 32 + mf * 16 + (lane >> 2);
            const int cc = nw * 64 + nf * 8 + ((lane & 3) << 1);
            *reinterpret_cast<float2*>(sg + r0 * 260 + cc) =
                make_float2(acc[mf][nf][0], acc[mf][nf][1]);
            *reinterpret_cast<float2*>(sg + (r0 + 8) * 260 + cc) =
                make_float2(acc[mf][nf][2], acc[mf][nf][3]);
        }
    __syncthreads();

#pragma unroll
    for (int e = 0; e < 16; ++e) {
        const int id = (e << 9) + (int)tid;           // 0..8191
        const int m = id >> 6;                        // 0..127
        const int j = id & 63;                        // 0..63
        const float zf = sg[m * 260 +        j] + __ldg(bf + j0 + j);
        const float zi = sg[m * 260 + 64   + j] + __ldg(bi + j0 + j);
        const float zg = sg[m * 260 + 128  + j] + __ldg(bg + j0 + j);
        const float zo = sg[m * 260 + 192  + j] + __ldg(bo + j0 + j);
        const float ft = 1.f / (1.f + __expf(-zf));
        const float it = 1.f / (1.f + __expf(-zi));
        const float gt = 2.f / (1.f + __expf(-2.f * zg)) - 1.f;
        const float ot = 1.f / (1.f + __expf(-zo));
        const size_t go = (size_t)(m0 + m) * HSZ + j0 + j;
        const float cn = ft * __ldg(cIn + go) + it * gt;
        const float hn = ot * (2.f / (1.f + __expf(-2.f * cn)) - 1.f);
        out[go] = hn;
        out[(size_t)BATCH * HSZ + go] = cn;
    }
}

// ============================================================================
// Launch
// ============================================================================
extern "C" void kernel_launch(void* const* d_in, const int* in_sizes, int n_in,
                              void* d_out, int out_size) {
    const float* x  = (const float*)d_in[0];
    const float* h  = (const float*)d_in[1];
    const float* c  = (const float*)d_in[2];
    const float* Wf = (const float*)d_in[3];
    const float* bf = (const float*)d_in[4];
    const float* Wi = (const float*)d_in[5];
    const float* bi = (const float*)d_in[6];
    const float* Wg = (const float*)d_in[7];
    const float* bg = (const float*)d_in[8];
    const float* Wo = (const float*)d_in[9];
    const float* bo = (const float*)d_in[10];
    float* out = (float*)d_out;

    cudaFuncSetAttribute(k_lstm, cudaFuncAttributeMaxDynamicSharedMemorySize,
                         SMEM_BYTES);

    k_convW<<<16384, 256>>>(Wf, Wi, Wg, Wo);
    k_convA<<<8192, 256>>>(h, x);
    k_lstm<<<1024, 512, SMEM_BYTES>>>(c, bf, bi, bg, bo, out);
}

// round 11
// speedup vs baseline: 1.3393x; 1.0270x over previous
#include <cuda_runtime.h>
#include <cuda_fp16.h>
#include <cstdint>

// ============================================================================
// Problem constants
// ============================================================================
#define BATCH 4096
#define HSZ   2048
#define KDIM  4096          // HSZ + INPUT_SIZE
#define NROWS 8192          // 4*HSZ gate-blocked weight rows

// GEMM tiling: CTA 128(M) x 256(N = 4 gates x 64 j), BK=64, 512 threads
#define TM 128
#define TN 256
#define BK 64
#define KT (KDIM / BK)      // 64 k-iterations
#define STAGES 4
#define STAGE_A (TM * BK * 2)            // 16384
#define STAGE_B (TN * BK * 2)            // 32768
#define STAGE_BYTES (STAGE_A + STAGE_B)  // 49152
#define CTRL_OFF (STAGES * STAGE_BYTES)  // 196608
#define SMEM_BYTES (1024 + CTRL_OFF + 64)

// fp16 staging in TILED+SWIZZLED layout (ready for cp.async.bulk):
//   g_A16t: tile t = mb*64+kt  (mb 0..31, kt 0..63), 128 rows x 64 k, 16KB each
//   g_W16t: tile t = nb*64+kt  (nb 0..31, kt 0..63), 256 nrows x 64 k, 32KB each
__device__ __half g_A16t[(size_t)BATCH * KDIM];   // 32 MB
__device__ __half g_W16t[(size_t)NROWS * KDIM];   // 64 MB

#define SW128(x) ((x) ^ (((x) >> 3) & 0x70))

// ============================================================================
// PTX helpers (base sm_90 features -> valid under compute_100 target)
// ============================================================================
__device__ __forceinline__ uint32_t s2u(const void* p) {
    uint32_t a;
    asm("{ .reg .u64 t; cvta.to.shared.u64 t, %1; cvt.u32.u64 %0, t; }"
        : "=r"(a) : "l"(p));
    return a;
}
#define MBAR_INIT(a, c) \
    asm volatile("mbarrier.init.shared.b64 [%0], %1;" :: "r"(a), "r"(c) : "memory")
#define MBAR_EXPECT_TX(a, b) \
    asm volatile("mbarrier.arrive.expect_tx.shared.b64 _, [%0], %1;" \
                 :: "r"(a), "r"(b) : "memory")
#define MBAR_WAIT(addr, ph) do {                                               \
    uint32_t _a = (addr), _p = (ph), _d;                                       \
    asm volatile("{ .reg .pred p; "                                            \
        "mbarrier.try_wait.parity.acquire.cta.shared::cta.b64 p, [%1], %2; "   \
        "selp.b32 %0, 1, 0, p; }" : "=r"(_d) : "r"(_a), "r"(_p) : "memory");   \
    if (!_d) {                                                                 \
        asm volatile("{ .reg .pred P; "                                        \
        "LW_%=: mbarrier.try_wait.parity.acquire.cta.shared::cta.b64 P, [%0], %1, 0x989680; " \
        "@P bra LD_%=; bra LW_%=; LD_%=: }" :: "r"(_a), "r"(_p) : "memory");   \
    } } while (0)

__device__ __forceinline__ void bulk_g2s(uint32_t dst, const void* src,
                                         uint32_t bytes, uint32_t mbar) {
    asm volatile(
        "cp.async.bulk.shared::cta.global.mbarrier::complete_tx::bytes "
        "[%0], [%1], %2, [%3];"
        :: "r"(dst), "l"(src), "r"(bytes), "r"(mbar) : "memory");
}
__device__ __forceinline__ void ldsm4(uint32_t (&r)[4], uint32_t addr) {
    asm volatile("ldmatrix.sync.aligned.m8n8.x4.shared.b16 {%0,%1,%2,%3}, [%4];"
                 : "=r"(r[0]), "=r"(r[1]), "=r"(r[2]), "=r"(r[3]) : "r"(addr));
}
__device__ __forceinline__ void mma16816(float (&c)[4], const uint32_t (&a)[4],
                                         uint32_t b0, uint32_t b1) {
    asm volatile(
        "mma.sync.aligned.m16n8k16.row.col.f32.f16.f16.f32 "
        "{%0,%1,%2,%3}, {%4,%5,%6,%7}, {%8,%9}, {%0,%1,%2,%3};"
        : "+f"(c[0]), "+f"(c[1]), "+f"(c[2]), "+f"(c[3])
        : "r"(a[0]), "r"(a[1]), "r"(a[2]), "r"(a[3]), "r"(b0), "r"(b1));
}

// ============================================================================
// fp32 -> fp16 conversion into tiled+swizzled layout
// ============================================================================
// A: chunk c -> tile(mb,kt), r(0..127), kc(0..7). 16B per chunk.
__global__ void __launch_bounds__(256) k_convA(
    const float* __restrict__ h, const float* __restrict__ x)
{
    const uint32_t c = blockIdx.x * 256u + threadIdx.x;   // < 2,097,152
    const uint32_t tile = c >> 10;                         // mb*64 + kt
    const uint32_t wi = c & 1023u;
    const uint32_t r = wi >> 3, kc = wi & 7u;
    const uint32_t mb = tile >> 6, kt = tile & 63u;
    const uint32_t m = mb * 128u + r;
    const uint32_t kg = kt * 64u + kc * 8u;
    const float* src = (kg < 2048u) ? (h + (size_t)m * 2048u + kg)
                                    : (x + (size_t)m * 2048u + (kg - 2048u));
    float4 v0 = *reinterpret_cast<const float4*>(src);
    float4 v1 = *reinterpret_cast<const float4*>(src + 4);
    union { __half2 h2[4]; uint4 u; } pk;
    pk.h2[0] = __floats2half2_rn(v0.x, v0.y);
    pk.h2[1] = __floats2half2_rn(v0.z, v0.w);
    pk.h2[2] = __floats2half2_rn(v1.x, v1.y);
    pk.h2[3] = __floats2half2_rn(v1.z, v1.w);
    char* dst = reinterpret_cast<char*>(g_A16t) + (size_t)tile * 16384u
              + SW128(r * 128u + kc * 16u);
    *reinterpret_cast<uint4*>(dst) = pk.u;
}

// W: chunk c -> tile(nb,kt), n_local(0..255)=gate*64+jl, kc(0..7)
__global__ void __launch_bounds__(256) k_convW(
    const float* __restrict__ Wf, const float* __restrict__ Wi,
    const float* __restrict__ Wg, const float* __restrict__ Wo)
{
    const uint32_t c = blockIdx.x * 256u + threadIdx.x;   // < 4,194,304
    const uint32_t tile = c >> 11;                         // nb*64 + kt
    const uint32_t wi = c & 2047u;
    const uint32_t nl = wi >> 3, kc = wi & 7u;
    const uint32_t nb = tile >> 6, kt = tile & 63u;
    const uint32_t gate = nl >> 6, jl = nl & 63u;
    const float* W = (gate == 0 ? Wf : gate == 1 ? Wi : gate == 2 ? Wg : Wo);
    const float* src = W + (size_t)(nb * 64u + jl) * KDIM + kt * 64u + kc * 8u;
    float4 v0 = *reinterpret_cast<const float4*>(src);
    float4 v1 = *reinterpret_cast<const float4*>(src + 4);
    union { __half2 h2[4]; uint4 u; } pk;
    pk.h2[0] = __floats2half2_rn(v0.x, v0.y);
    pk.h2[1] = __floats2half2_rn(v0.z, v0.w);
    pk.h2[2] = __floats2half2_rn(v1.x, v1.y);
    pk.h2[3] = __floats2half2_rn(v1.z, v1.w);
    char* dst = reinterpret_cast<char*>(g_W16t) + (size_t)tile * 32768u
              + SW128(nl * 128u + kc * 16u);
    *reinterpret_cast<uint4*>(dst) = pk.u;
}

// ============================================================================
// Fused LSTM: 128x256 CTA tile, 32x64 warp tiles (4x4 warps), 512 threads.
// Paired-stage pipeline: 2 pairs x 2 stages, ONE mbar wait + ONE bar.sync +
// ONE producer issue per 2 kt.
// grid = 1024 (bx>>5 = m-tile, bx&31 = j-tile)
// ============================================================================
__global__ void __launch_bounds__(512, 1) k_lstm(
    const float* __restrict__ cIn,
    const float* __restrict__ bf, const float* __restrict__ bi,
    const float* __restrict__ bg, const float* __restrict__ bo,
    float* __restrict__ out)
{
    extern __shared__ char smem[];
    const uint32_t raw  = s2u(smem);
    const uint32_t base = (raw + 1023u) & ~1023u;     // 1KB aligned stages
    const uint32_t ctrl = base + CTRL_OFF;            // 2 pair-mbarriers
    const uint32_t tid  = threadIdx.x;
    const int wid  = tid >> 5;
    const int lane = tid & 31;
    const int mw = wid >> 2;          // 0..3  (M warp: 32 rows)
    const int nw = wid & 3;           // 0..3  (N warp: 64 cols)

    const int mb = blockIdx.x >> 5;
    const int nb = blockIdx.x & 31;
    const int m0 = mb * TM;
    const int j0 = nb * 64;

    const char* gA = reinterpret_cast<const char*>(g_A16t)
                   + (size_t)(mb * 64) * 16384u;       // + kt*16384
    const char* gB = reinterpret_cast<const char*>(g_W16t)
                   + (size_t)(nb * 64) * 32768u;       // + kt*32768

    if (tid == 0) {
        MBAR_INIT(ctrl + 0, 1);
        MBAR_INIT(ctrl + 8, 1);
    }
    __syncthreads();

    // prologue: fill both pairs (stages 0..3 = kt 0..3)
    if (tid == 0) {
#pragma unroll
        for (int p = 0; p < 2; ++p) {
            MBAR_EXPECT_TX(ctrl + p * 8, 2u * STAGE_BYTES);
#pragma unroll
            for (int q = 0; q < 2; ++q) {
                const int st = p * 2 + q;              // stage = kt for prologue
                const uint32_t sb = base + st * STAGE_BYTES;
                bulk_g2s(sb, gA + (size_t)st * 16384u, STAGE_A, ctrl + p * 8);
                bulk_g2s(sb + STAGE_A, gB + (size_t)st * 32768u, STAGE_B,
                         ctrl + p * 8);
            }
        }
    }

    float acc[2][8][4];
#pragma unroll
    for (int a = 0; a < 2; ++a)
#pragma unroll
        for (int b = 0; b < 8; ++b)
#pragma unroll
            for (int c = 0; c < 4; ++c) acc[a][b][c] = 0.f;

    const int ldRow = lane & 15;
    const int ldKB  = (lane >> 4) << 4;

    // one-stage compute body
    auto compute_stage = [&](uint32_t sA) {
        const uint32_t sB = sA + STAGE_A;
#pragma unroll
        for (int ks = 0; ks < 4; ++ks) {              // 4 x k16 per BK=64
            const uint32_t kb = ks << 5;
            uint32_t afr[2][4];
#pragma unroll
            for (int mf = 0; mf < 2; ++mf)
                ldsm4(afr[mf], sA + SW128((uint32_t)((mw * 32 + mf * 16 + ldRow) * 128)
                                          + kb + ldKB));
            uint32_t bfr[4][4];
#pragma unroll
            for (int pr = 0; pr < 4; ++pr)
                ldsm4(bfr[pr], sB + SW128((uint32_t)((nw * 64 + pr * 16 + ldRow) * 128)
                                          + kb + ldKB));
#pragma unroll
            for (int mf = 0; mf < 2; ++mf)
#pragma unroll
                for (int nf = 0; nf < 8; ++nf) {
                    const int pr = nf >> 1, sub = nf & 1;
                    mma16816(acc[mf][nf], afr[mf], bfr[pr][sub], bfr[pr][sub + 2]);
                }
        }
    };

    // ---------------- main loop: 32 super-iterations of 2 kt ----------------
    for (int T = 0; T < KT / 2; ++T) {
        const int p = T & 1;                           // pair index
        MBAR_WAIT(ctrl + p * 8, (T >> 1) & 1);

        compute_stage(base + (p * 2 + 0) * STAGE_BYTES);   // kt = 2T
        compute_stage(base + (p * 2 + 1) * STAGE_BYTES);   // kt = 2T+1

        __syncthreads();                               // all warps done with pair p

        if (tid == 0 && T + 2 < KT / 2) {
            const int nk = 2 * (T + 2);                // refill pair p for T+2
            MBAR_EXPECT_TX(ctrl + p * 8, 2u * STAGE_BYTES);
#pragma unroll
            for (int q = 0; q < 2; ++q) {
                const uint32_t sb = base + (p * 2 + q) * STAGE_BYTES;
                bulk_g2s(sb, gA + (size_t)(nk + q) * 16384u, STAGE_A, ctrl + p * 8);
                bulk_g2s(sb + STAGE_A, gB + (size_t)(nk + q) * 32768u, STAGE_B,
                         ctrl + p * 8);
            }
        }
    }

    // ---------------- epilogue ----------------
    __syncthreads();                                  // compute done before alias
    float* sg = reinterpret_cast<float*>(smem + (base - raw));   // [128][260]

#pragma unroll
    for (int mf = 0; mf < 2; ++mf)
#pragma unroll
        for (int nf = 0; nf < 8; ++nf) {
            const int r0 = mw * 32 + mf * 16 + (lane >> 2);
            const int cc = nw * 64 + nf * 8 + ((lane & 3) << 1);
            *reinterpret_cast<float2*>(sg + r0 * 260 + cc) =
                make_float2(acc[mf][nf][0], acc[mf][nf][1]);
            *reinterpret_cast<float2*>(sg + (r0 + 8) * 260 + cc) =
                make_float2(acc[mf][nf][2], acc[mf][nf][3]);
        }
    __syncthreads();

#pragma unroll
    for (int e = 0; e < 16; ++e) {
        const int id = (e << 9) + (int)tid;           // 0..8191
        const int m = id >> 6;                        // 0..127
        const int j = id & 63;                        // 0..63
        const float zf = sg[m * 260 +        j] + __ldg(bf + j0 + j);
        const float zi = sg[m * 260 + 64   + j] + __ldg(bi + j0 + j);
        const float zg = sg[m * 260 + 128  + j] + __ldg(bg + j0 + j);
        const float zo = sg[m * 260 + 192  + j] + __ldg(bo + j0 + j);
        const float ft = 1.f / (1.f + __expf(-zf));
        const float it = 1.f / (1.f + __expf(-zi));
        const float gt = 2.f / (1.f + __expf(-2.f * zg)) - 1.f;
        const float ot = 1.f / (1.f + __expf(-zo));
        const size_t go = (size_t)(m0 + m) * HSZ + j0 + j;
        const float cn = ft * __ldg(cIn + go) + it * gt;
        const float hn = ot * (2.f / (1.f + __expf(-2.f * cn)) - 1.f);
        out[go] = hn;
        out[(size_t)BATCH * HSZ + go] = cn;
    }
}

// ============================================================================
// Launch
// ============================================================================
extern "C" void kernel_launch(void* const* d_in, const int* in_sizes, int n_in,
                              void* d_out, int out_size) {
    const float* x  = (const float*)d_in[0];
    const float* h  = (const float*)d_in[1];
    const float* c  = (const float*)d_in[2];
    const float* Wf = (const float*)d_in[3];
    const float* bf = (const float*)d_in[4];
    const float* Wi = (const float*)d_in[5];
    const float* bi = (const float*)d_in[6];
    const float* Wg = (const float*)d_in[7];
    const float* bg = (const float*)d_in[8];
    const float* Wo = (const float*)d_in[9];
    const float* bo = (const float*)d_in[10];
    float* out = (float*)d_out;

    cudaFuncSetAttribute(k_lstm, cudaFuncAttributeMaxDynamicSharedMemorySize,
                         SMEM_BYTES);

    k_convW<<<16384, 256>>>(Wf, Wi, Wg, Wo);
    k_convA<<<8192, 256>>>(h, x);
    k_lstm<<<1024, 512, SMEM_BYTES>>>(c, bf, bi, bg, bo, out);
}